// round 14
// baseline (speedup 1.0000x reference)
#include <cuda_runtime.h>
#include <cuda_bf16.h>
#include <cuda_fp8.h>
#include <math.h>
#include <stdint.h>

// Problem constants
#define VOCAB   50000
#define N_SEQ   4096
#define N_DOCS  512
#define EMBD    300
#define HID     256
#define GATES   1024
#define T_COL   64
#define T_ROW   16

#define MCH     16          // sequences per chunk (one 2-CTA cluster)
#define NT      256         // 8 warps per CTA

#define NKT_H   8
// xproj A (emb, fp8): k=300 pad 320 -> 10 kt, row stride 336 B (84 words)
#define NKT_X   10
#define XKW     84
#define XSB     336
#define XBLK    782         // ceil(50000/64)

#define SCL     16.0f
#define ISCL    0.00390625f // 1/256

// ---------------- device scratch ----------------
// Whh fragments, pair-interleaved for LDG.128: [mat][kt][pair(64)][lane][2 tiles]
__device__ uint2  g_Whh2[2][NKT_H][64][32][2];
__device__ uint2  g_Wih[2][NKT_X][128][32];    // fp8 B fragments (x-proj)
__device__ float  g_bias[2][GATES];
// xproj in fragment-word order: word w' = P*8 + tg*2 + eo  (P=pair, eo: 0=(i,f),1=(g,o))
__device__ uint32_t g_xprojF[2][VOCAB][512];   // 204.8 MB
__device__ float  g_acc[3][N_DOCS][HID];

// permuted column -> original gate column:
//   p = j'>>3 (tile), c = j'&7;  gate = (p&1)*2 + (c&1);  unit = 4*(p>>1) + (c>>1)
__device__ __forceinline__ int perm_to_orig(int jp) {
    int p = jp >> 3, c = jp & 7;
    int gate = ((p & 1) << 1) | (c & 1);
    int unit = ((p >> 1) << 2) | (c >> 1);
    return gate * 256 + unit;
}

// ---------------- helpers ----------------
__device__ __forceinline__ float ftanh(float x) {
    float y; asm("tanh.approx.f32 %0, %1;" : "=f"(y) : "f"(x)); return y;
}
__device__ __forceinline__ float fsigm(float x) {
    return 0.5f * ftanh(0.5f * x) + 0.5f;
}
__device__ __forceinline__ uint32_t pack4_e4m3(float v0, float v1, float v2, float v3) {
    uint16_t lo, hi;
    asm("cvt.rn.satfinite.e4m3x2.f32 %0, %1, %2;" : "=h"(lo) : "f"(v1), "f"(v0));
    asm("cvt.rn.satfinite.e4m3x2.f32 %0, %1, %2;" : "=h"(hi) : "f"(v3), "f"(v2));
    return (uint32_t)lo | ((uint32_t)hi << 16);
}
__device__ __forceinline__ uint8_t f_to_e4m3(float v) {
    uint16_t r;
    asm("cvt.rn.satfinite.e4m3x2.f32 %0, %1, %2;" : "=h"(r) : "f"(0.f), "f"(v));
    return (uint8_t)r;
}
__device__ __forceinline__ uint32_t pack_bf16x2(float lo, float hi) {
    uint32_t r;
    asm("cvt.rn.bf16x2.f32 %0, %1, %2;" : "=r"(r) : "f"(hi), "f"(lo));
    return r;
}
__device__ __forceinline__ void mma16832(float* c, const uint32_t* a, uint32_t b0, uint32_t b1) {
    asm volatile(
        "mma.sync.aligned.m16n8k32.row.col.f32.e4m3.e4m3.f32 "
        "{%0,%1,%2,%3},{%4,%5,%6,%7},{%8,%9},{%0,%1,%2,%3};"
        : "+f"(c[0]), "+f"(c[1]), "+f"(c[2]), "+f"(c[3])
        : "r"(a[0]), "r"(a[1]), "r"(a[2]), "r"(a[3]), "r"(b0), "r"(b1));
}
__device__ __forceinline__ uint32_t smem_u32(const void* p) {
    uint32_t a;
    asm("{ .reg .u64 t; cvta.to.shared.u64 t, %1; cvt.u32.u64 %0, t; }" : "=r"(a) : "l"(p));
    return a;
}

// ---------------- prep: pack weights + bias, zero accumulators ----------------
__global__ void prep_kernel(const float* cWih, const float* cWhh,
                            const float* cbih, const float* cbhh,
                            const float* rWih, const float* rWhh,
                            const float* rbih, const float* rbhh,
                            float* out) {
    int idx = blockIdx.x * blockDim.x + threadIdx.x;   // 393216 threads
    if (idx == 0) *out = 0.f;
    if (idx < 3 * N_DOCS * HID) (&g_acc[0][0][0])[idx] = 0.f;

    if (idx < 2 * GATES) {
        int bm = idx >> 10, jb = idx & 1023;
        int jbo = perm_to_orig(jb);
        const float* bih = bm ? rbih : cbih;
        const float* bhh = bm ? rbhh : cbhh;
        g_bias[bm][jb] = bih[jbo] + bhh[jbo];
    }

    int lane = idx & 31;
    int ntg  = (idx >> 5) & 127;
    int q    = idx >> 12;
    int tg = lane & 3, gg = lane >> 2;
    int jo = perm_to_orig(ntg * 8 + gg);

    if (idx < 2 * NKT_X * 128 * 32) {           // Wih pack (k 0..299 pad 320)
        int kt  = q % NKT_X;
        int mat = q / NKT_X;
        const float* Wih = mat ? rWih : cWih;
        int k0 = kt * 32 + 4 * tg;
        float v[8];
        #pragma unroll
        for (int i = 0; i < 8; i++) {
            int k = k0 + (i >> 2) * 16 + (i & 3);
            v[i] = (k < EMBD) ? SCL * Wih[jo * EMBD + k] : 0.f;
        }
        uint2 w2;
        w2.x = pack4_e4m3(v[0], v[1], v[2], v[3]);
        w2.y = pack4_e4m3(v[4], v[5], v[6], v[7]);
        g_Wih[mat][kt][ntg][lane] = w2;
    }
    if (idx < 2 * NKT_H * 128 * 32) {           // Whh pack, pair-interleaved
        int kt  = q % NKT_H;
        int mat = q / NKT_H;
        const float* Whh = mat ? rWhh : cWhh;
        int k0 = kt * 32 + 4 * tg;
        float v[8];
        #pragma unroll
        for (int i = 0; i < 8; i++) {
            int k = k0 + (i >> 2) * 16 + (i & 3);
            v[i] = SCL * Whh[jo * HID + k];
        }
        uint2 w2;
        w2.x = pack4_e4m3(v[0], v[1], v[2], v[3]);
        w2.y = pack4_e4m3(v[4], v[5], v[6], v[7]);
        g_Whh2[mat][kt][ntg >> 1][lane][ntg & 1] = w2;
    }
}

__global__ void dummy_kernel() {}

// ---------------- xproj: 64 vocab rows/block, 512 threads, shared B stream ----------------
__global__ void __launch_bounds__(512, 1)
xproj_kernel(const float* emb) {
    __shared__ uint8_t As[64 * XSB];       // 21504 B
    int bid = blockIdx.x;                  // 2 * XBLK
    int mat = bid >= XBLK;
    int vbase = (bid - mat * XBLK) * 64;

    int tid = threadIdx.x;
    int w = tid >> 5, lane = tid & 31;
    int wg = w >> 3;                       // row group 0/1 (rows wg*32..wg*32+31)
    int wi = w & 7;                        // tile group
    int tg = lane & 3, gg = lane >> 2;

    for (int i = tid; i < 64 * XSB / 4; i += 512) ((uint32_t*)As)[i] = 0u;
    __syncthreads();

    {   // gather embeddings -> fp8 (x16): 8 threads per row, 64 rows
        int m = tid >> 3, ts = tid & 7;
        int row = vbase + m; if (row >= VOCAB) row = 0;
        const float4* erow = (const float4*)(emb + (size_t)row * EMBD);
        uint32_t* arow = (uint32_t*)(As + m * XSB);
        for (int kk = ts; kk < EMBD / 4; kk += 8) {
            float4 v = __ldg(&erow[kk]);
            arow[kk] = pack4_e4m3(SCL * v.x, SCL * v.y, SCL * v.z, SCL * v.w);
        }
    }
    __syncthreads();

    const uint32_t* Aw = (const uint32_t*)As;
    const int a_base = (wg * 32 + gg) * XKW + tg;

    #pragma unroll
    for (int h = 0; h < 2; h++) {
        int nt_base = (wi << 4) + (h << 3);
        const uint2* Bp = &g_Wih[mat][0][0][0] + nt_base * 32 + lane;

        float acc[2][8][4];
        #pragma unroll
        for (int mt = 0; mt < 2; mt++)
            #pragma unroll
            for (int nt = 0; nt < 8; nt++)
                #pragma unroll
                for (int i = 0; i < 4; i++) acc[mt][nt][i] = 0.f;

        uint2 bb[8];
        #pragma unroll
        for (int nt = 0; nt < 8; nt++) bb[nt] = __ldg(Bp + nt * 32);
        #pragma unroll
        for (int kt = 0; kt < NKT_X; kt++) {
            uint2 bn[8];
            if (kt < NKT_X - 1) {
                const uint2* bk2 = Bp + (size_t)(kt + 1) * 128 * 32;
                #pragma unroll
                for (int nt = 0; nt < 8; nt++) bn[nt] = __ldg(bk2 + nt * 32);
            }
            uint32_t a[2][4];
            int ab = a_base + kt * 8;
            #pragma unroll
            for (int mt = 0; mt < 2; mt++) {
                int o = ab + mt * 16 * XKW;
                a[mt][0] = Aw[o];
                a[mt][1] = Aw[o + 8 * XKW];
                a[mt][2] = Aw[o + 4];
                a[mt][3] = Aw[o + 8 * XKW + 4];
            }
            #pragma unroll
            for (int nt = 0; nt < 8; nt++) {
                mma16832(acc[0][nt], a[0], bb[nt].x, bb[nt].y);
                mma16832(acc[1][nt], a[1], bb[nt].x, bb[nt].y);
            }
            #pragma unroll
            for (int nt = 0; nt < 8; nt++) bb[nt] = bn[nt];
        }

        // epilogue: +bias, store bf16x2 in fragment-word order
        #pragma unroll
        for (int nt = 0; nt < 8; nt++) {
            int tile = nt_base + nt;
            int jc = (tile << 3) + (tg << 1);
            int wp = ((tile >> 1) << 3) + (tg << 1) + (tile & 1);   // fragment word index
            float b0 = g_bias[mat][jc], b1 = g_bias[mat][jc + 1];
            #pragma unroll
            for (int mt = 0; mt < 2; mt++) {
                int r0 = vbase + wg * 32 + (mt << 4) + gg;
                int r1 = r0 + 8;
                if (r0 < VOCAB)
                    g_xprojF[mat][r0][wp] =
                        pack_bf16x2(acc[mt][nt][0] * ISCL + b0, acc[mt][nt][1] * ISCL + b1);
                if (r1 < VOCAB)
                    g_xprojF[mat][r1][wp] =
                        pack_bf16x2(acc[mt][nt][2] * ISCL + b0, acc[mt][nt][3] * ISCL + b1);
            }
        }
    }
}

// ---------------- main recurrent LSTM kernel: 2-CTA cluster split-N, bulk DSMEM exchange ----------------
__global__ void __cluster_dims__(2, 1, 1) __launch_bounds__(NT, 2)
lstm_kernel(const int* colT, const int* rowT, const int* negT,
            const int* clen, const int* rlen, const int* nlen,
            const int* cref, const int* rref, const int* nref) {
    // A buffers in fragment-major order: byte addr = kt*512 + lane*16 + j*4 + b
    __shared__ __align__(16) uint8_t  AsF0[NKT_H * 512];     // 4096
    __shared__ __align__(16) uint8_t  AsF1[NKT_H * 512];     // 4096
    __shared__ __nv_bfloat16  Hs[MCH * 264];         // 8448
    __shared__ int            toksAll[MCH * T_COL];  // 4096
    __shared__ int            lensS[MCH];
    __shared__ int            refS[MCH];
    __shared__ uint64_t       mbar;

    uint32_t rank;
    asm("mov.u32 %0, %%cluster_ctarank;" : "=r"(rank));

    // LPT map on cluster id (CLC contiguous placement: cluster c co-resident with c+74)
    int cid = blockIdx.x >> 1;
    int task, chunk;
    if (cid < 74)        { task = 0; chunk = cid; }           // long cols 0..73
    else if (cid < 148)  { task = 0; chunk = 329 - cid; }     // 255..182 (pairs long)
    else if (cid < 222)  { task = 0; chunk = cid - 74; }      // 74..147
    else if (cid < 256)  { task = 0; chunk = 403 - cid; }     // 181..148
    else { int s = cid - 256; task = 1 + (s & 1); chunk = s >> 1; }
    int n0 = chunk * MCH;

    const int* toks; const int* lens; const int* refs; int T; int mat;
    if (task == 0)      { toks = colT; lens = clen; refs = cref; T = T_COL; mat = 0; }
    else if (task == 1) { toks = rowT; lens = rlen; refs = rref; T = T_ROW; mat = 1; }
    else                { toks = negT; lens = nlen; refs = nref; T = T_ROW; mat = 1; }

    int tid = threadIdx.x;
    int w = tid >> 5, lane = tid & 31;
    int tg = lane & 3, gg = lane >> 2;

    // init: zero AsF0; load all tokens + lens; init mbarrier
    for (int i = tid; i < NKT_H * 512 / 4; i += NT) ((uint32_t*)AsF0)[i] = 0u;
    for (int i = tid; i < MCH * T; i += NT) toksAll[i] = toks[n0 * T + i];
    if (tid < MCH) lensS[tid] = lens[n0 + tid];
    uint32_t mbarA = smem_u32(&mbar);
    if (tid == 0) {
        asm volatile("mbarrier.init.shared.b64 [%0], %1;" :: "r"(mbarA), "r"(2 * NT) : "memory");
    }

    // peer addresses via mapa
    uint32_t peer = rank ^ 1u;
    uint32_t myAs0 = smem_u32(AsF0), myAs1 = smem_u32(AsF1);
    uint32_t pAs0, pAs1, pMbar;
    asm("mapa.shared::cluster.u32 %0, %1, %2;" : "=r"(pAs0) : "r"(myAs0), "r"(peer));
    asm("mapa.shared::cluster.u32 %0, %1, %2;" : "=r"(pAs1) : "r"(myAs1), "r"(peer));
    asm("mapa.shared::cluster.u32 %0, %1, %2;" : "=r"(pMbar) : "r"(mbarA), "r"(peer));

    // cluster sync: mbarriers + zeroed A visible before any arrivals / reads
    asm volatile("barrier.cluster.arrive.aligned;" ::: "memory");
    asm volatile("barrier.cluster.wait.aligned;" ::: "memory");

    int maxlen = lensS[0];    // lengths sorted descending (same for both CTAs)
    int len0 = lensS[gg], len1 = lensS[gg + 8];

    const uint32_t* xpF = &g_xprojF[mat][0][0];
    const uint4* Bq = (const uint4*)&g_Whh2[mat][0][0][0][0];  // [kt*64 + pair]*32 + lane
    int p0 = (int)rank * 32 + (w << 2);    // this warp's 4 global pairs

    // my contiguous half of the A buffer: bytes [rank*2048, rank*2048+2048)
    uint32_t xoff = ((uint32_t)rank << 11) + ((uint32_t)tid << 3);

    // cell state in registers: [pair 0..3][row r]
    float creg[4][2];
    #pragma unroll
    for (int p = 0; p < 4; p++) { creg[p][0] = 0.f; creg[p][1] = 0.f; }

    for (int t = 0; t < maxlen; t++) {
        const uint8_t* ArF = (t & 1) ? AsF1 : AsF0;
        uint8_t*       AwF = (t & 1) ? AsF0 : AsF1;
        uint32_t       pAw = (t & 1) ? pAs0 : pAs1;
        const uint4*   Ar4 = (const uint4*)ArF;

        int tk0 = toksAll[gg * T + t];
        int tk1 = toksAll[(gg + 8) * T + t];
        const uint32_t* xp0w = xpF + (size_t)tk0 * 512;
        const uint32_t* xp1w = xpF + (size_t)tk1 * 512;

        // gx: one LDG.64 per (pair, token)
        uint2 gq0[4], gq1[4];
        #pragma unroll
        for (int pp = 0; pp < 4; pp++) {
            int woff = ((p0 + pp) << 3) + (tg << 1);
            gq0[pp] = __ldg((const uint2*)(xp0w + woff));
            gq1[pp] = __ldg((const uint2*)(xp1w + woff));
        }

        float acc[8][4];
        #pragma unroll
        for (int nt = 0; nt < 8; nt++)
            #pragma unroll
            for (int i = 0; i < 4; i++) acc[nt][i] = 0.f;

        // 2-stage B pipeline: 4 LDG.128 per kt (one per pair)
        uint4 bb[4], bn[4];
        #pragma unroll
        for (int pp = 0; pp < 4; pp++) bb[pp] = __ldg(&Bq[(0 * 64 + p0 + pp) * 32 + lane]);
        #pragma unroll
        for (int kt = 0; kt < NKT_H; kt++) {
            if (kt < NKT_H - 1) {
                #pragma unroll
                for (int pp = 0; pp < 4; pp++)
                    bn[pp] = __ldg(&Bq[((kt + 1) * 64 + p0 + pp) * 32 + lane]);
            }
            uint4 av = Ar4[kt * 32 + lane];          // one LDS.128: a0..a3
            uint32_t a[4] = {av.x, av.y, av.z, av.w};
            #pragma unroll
            for (int pp = 0; pp < 4; pp++) {
                mma16832(acc[2 * pp],     a, bb[pp].x, bb[pp].y);
                mma16832(acc[2 * pp + 1], a, bb[pp].z, bb[pp].w);
            }
            #pragma unroll
            for (int pp = 0; pp < 4; pp++) bb[pp] = bn[pp];
        }

        // epilogue: shuffle-free; local writes only
        #pragma unroll
        for (int pp = 0; pp < 4; pp++) {
            int P = p0 + pp;
            int abase = ((P >> 3) << 9) + ((gg << 2) + (P & 3)) * 16
                      + (((P >> 2) & 1) << 3) + tg;
            #pragma unroll
            for (int r = 0; r < 2; r++) {
                int cb = r << 1;
                uint32_t ew = r ? gq1[pp].x : gq0[pp].x;
                uint32_t ow = r ? gq1[pp].y : gq0[pp].y;
                float2 e2 = __bfloat1622float2(*(__nv_bfloat162*)&ew);
                float2 o2 = __bfloat1622float2(*(__nv_bfloat162*)&ow);
                float pi = acc[2 * pp][cb]     * ISCL + e2.x;
                float pf = acc[2 * pp][cb + 1] * ISCL + e2.y;
                float pg = acc[2 * pp + 1][cb]     * ISCL + o2.x;
                float po = acc[2 * pp + 1][cb + 1] * ISCL + o2.y;
                int lenm = r ? len1 : len0;
                int ai = abase + (r << 2);
                uint8_t val;
                if (t < lenm) {
                    float cn = fsigm(pf) * creg[pp][r] + fsigm(pi) * ftanh(pg);
                    creg[pp][r] = cn;
                    float hn = fsigm(po) * ftanh(cn);
                    val = f_to_e4m3(SCL * hn);
                    if (t == lenm - 1) {
                        int mrow = gg + (r << 3);
                        int u = (P << 2) + tg;
                        Hs[mrow * 264 + u] = __float2bfloat16(hn);
                    }
                } else {
                    val = ArF[ai];   // carry frozen h forward
                }
                AwF[ai] = val;
            }
        }

        // local writes visible, then bulk-copy my contiguous 2KB half to peer
        __syncthreads();
        {
            uint64_t v64 = *(const uint64_t*)(AwF + xoff);
            asm volatile("st.shared::cluster.u64 [%0], %1;"
                         :: "r"(pAw + xoff), "l"(v64) : "memory");
        }

        // per-step cluster sync via mbarrier (release orders the remote stores)
        asm volatile("mbarrier.arrive.release.cluster.shared::cluster.b64 _, [%0];"
                     :: "r"(pMbar) : "memory");
        asm volatile("mbarrier.arrive.release.cluster.shared::cta.b64 _, [%0];"
                     :: "r"(mbarA) : "memory");
        {
            uint32_t par = (uint32_t)(t & 1);
            uint32_t done = 0;
            while (!done) {
                asm volatile(
                    "{\n\t.reg .pred p;\n\t"
                    "mbarrier.try_wait.parity.acquire.cluster.shared::cta.b64 p, [%1], %2;\n\t"
                    "selp.b32 %0, 1, 0, p;\n\t}"
                    : "=r"(done) : "r"(mbarA), "r"(par) : "memory");
            }
        }
    }

    // scatter this CTA's half of final h into doc accumulators
    if (tid < MCH) refS[tid] = refs[n0 + tid];
    __syncthreads();
    float* accb = &g_acc[task][0][0];
    for (int idx = tid; idx < MCH * 128; idx += NT) {
        int m = idx >> 7;
        int u = (int)rank * 128 + (idx & 127);
        atomicAdd(&accb[refS[m] * HID + u], __bfloat162float(Hs[m * 264 + u]));
    }

    // final cluster sync before teardown
    asm volatile("barrier.cluster.arrive.aligned;" ::: "memory");
    asm volatile("barrier.cluster.wait.aligned;" ::: "memory");
}

// ---------------- loss ----------------
__global__ void loss_kernel(float* out) {
    int d = blockIdx.x;
    float cv = g_acc[0][d][threadIdx.x], rv = g_acc[1][d][threadIdx.x], nv = g_acc[2][d][threadIdx.x];
    float p = cv * rv, q = cv * nv;
    #pragma unroll
    for (int o = 16; o; o >>= 1) {
        p += __shfl_xor_sync(0xffffffffu, p, o);
        q += __shfl_xor_sync(0xffffffffu, q, o);
    }
    __shared__ float sp[8], sq[8];
    int w = threadIdx.x >> 5, l = threadIdx.x & 31;
    if (l == 0) { sp[w] = p; sq[w] = q; }
    __syncthreads();
    if (threadIdx.x == 0) {
        float P = 0.f, Q = 0.f;
        #pragma unroll
        for (int i = 0; i < 8; i++) { P += sp[i]; Q += sq[i]; }
        float x = P - Q;
        float lz = fmaxf(-x, 0.f) + log1pf(expf(-fabsf(x)));
        if (d == 0) lz += (float)((N_SEQ - N_DOCS) * 0.6931471805599453);
        atomicAdd(out, lz);
    }
}

// ---------------- launch ----------------
extern "C" void kernel_launch(void* const* d_in, const int* in_sizes, int n_in,
                              void* d_out, int out_size) {
    const int*   col   = (const int*)d_in[0];
    const int*   row   = (const int*)d_in[1];
    const int*   rng   = (const int*)d_in[2];
    const int*   clen  = (const int*)d_in[3];
    const int*   rlen  = (const int*)d_in[4];
    const int*   nlen  = (const int*)d_in[5];
    const int*   cref  = (const int*)d_in[6];
    const int*   rref  = (const int*)d_in[7];
    const int*   nref  = (const int*)d_in[8];
    const float* emb   = (const float*)d_in[9];
    const float* cWih  = (const float*)d_in[10];
    const float* cWhh  = (const float*)d_in[11];
    const float* cbih  = (const float*)d_in[12];
    const float* cbhh  = (const float*)d_in[13];
    const float* rWih  = (const float*)d_in[14];
    const float* rWhh  = (const float*)d_in[15];
    const float* rbih  = (const float*)d_in[16];
    const float* rbhh  = (const float*)d_in[17];
    float* out = (float*)d_out;

    prep_kernel<<<1536, 256>>>(cWih, cWhh, cbih, cbhh, rWih, rWhh, rbih, rbhh, out);
    xproj_kernel<<<2 * XBLK, 512>>>(emb);
    dummy_kernel<<<1, 32>>>();
    lstm_kernel<<<1536, NT>>>(col, row, rng, clen, rlen, nlen, cref, rref, nref);
    loss_kernel<<<N_DOCS, 256>>>(out);
}

// round 15
// speedup vs baseline: 1.0536x; 1.0536x over previous
#include <cuda_runtime.h>
#include <cuda_bf16.h>
#include <cuda_fp8.h>
#include <math.h>
#include <stdint.h>

// Problem constants
#define VOCAB   50000
#define N_SEQ   4096
#define N_DOCS  512
#define EMBD    300
#define HID     256
#define GATES   1024
#define T_COL   64
#define T_ROW   16

#define MCH     16          // sequences per chunk (one 2-CTA cluster)
#define NT      256         // 8 warps per CTA

#define NKT_H   8
// xproj A (emb, fp8): k=300 pad 320 -> 10 kt, row stride 336 B (84 words)
#define NKT_X   10
#define XKW     84
#define XSB     336

#define SCL     16.0f
#define ISCL    0.00390625f // 1/256

// ---------------- device scratch ----------------
// Whh fragments, pair-interleaved for LDG.128: [mat][kt][pair(64)][lane][2 tiles]
__device__ uint2  g_Whh2[2][NKT_H][64][32][2];
__device__ uint2  g_Wih[2][NKT_X][128][32];    // fp8 B fragments (x-proj)
__device__ float  g_bias[2][GATES];
// xproj in fragment-word order: word w' = P*8 + tg*2 + eo  (P=pair, eo: 0=(i,f),1=(g,o))
__device__ uint32_t g_xprojF[2][VOCAB][512];   // 204.8 MB
__device__ float  g_acc[3][N_DOCS][HID];

// permuted column -> original gate column:
//   p = j'>>3 (tile), c = j'&7;  gate = (p&1)*2 + (c&1);  unit = 4*(p>>1) + (c>>1)
__device__ __forceinline__ int perm_to_orig(int jp) {
    int p = jp >> 3, c = jp & 7;
    int gate = ((p & 1) << 1) | (c & 1);
    int unit = ((p >> 1) << 2) | (c >> 1);
    return gate * 256 + unit;
}

// ---------------- helpers ----------------
__device__ __forceinline__ float ftanh(float x) {
    float y; asm("tanh.approx.f32 %0, %1;" : "=f"(y) : "f"(x)); return y;
}
__device__ __forceinline__ float fsigm(float x) {
    return 0.5f * ftanh(0.5f * x) + 0.5f;
}
__device__ __forceinline__ uint32_t pack4_e4m3(float v0, float v1, float v2, float v3) {
    uint16_t lo, hi;
    asm("cvt.rn.satfinite.e4m3x2.f32 %0, %1, %2;" : "=h"(lo) : "f"(v1), "f"(v0));
    asm("cvt.rn.satfinite.e4m3x2.f32 %0, %1, %2;" : "=h"(hi) : "f"(v3), "f"(v2));
    return (uint32_t)lo | ((uint32_t)hi << 16);
}
__device__ __forceinline__ uint8_t f_to_e4m3(float v) {
    uint16_t r;
    asm("cvt.rn.satfinite.e4m3x2.f32 %0, %1, %2;" : "=h"(r) : "f"(0.f), "f"(v));
    return (uint8_t)r;
}
__device__ __forceinline__ uint32_t pack_bf16x2(float lo, float hi) {
    uint32_t r;
    asm("cvt.rn.bf16x2.f32 %0, %1, %2;" : "=r"(r) : "f"(hi), "f"(lo));
    return r;
}
__device__ __forceinline__ void mma16832(float* c, const uint32_t* a, uint32_t b0, uint32_t b1) {
    asm volatile(
        "mma.sync.aligned.m16n8k32.row.col.f32.e4m3.e4m3.f32 "
        "{%0,%1,%2,%3},{%4,%5,%6,%7},{%8,%9},{%0,%1,%2,%3};"
        : "+f"(c[0]), "+f"(c[1]), "+f"(c[2]), "+f"(c[3])
        : "r"(a[0]), "r"(a[1]), "r"(a[2]), "r"(a[3]), "r"(b0), "r"(b1));
}
__device__ __forceinline__ uint32_t smem_u32(const void* p) {
    uint32_t a;
    asm("{ .reg .u64 t; cvta.to.shared.u64 t, %1; cvt.u32.u64 %0, t; }" : "=r"(a) : "l"(p));
    return a;
}

// ---------------- prep: pack weights + bias, zero accumulators ----------------
__global__ void prep_kernel(const float* cWih, const float* cWhh,
                            const float* cbih, const float* cbhh,
                            const float* rWih, const float* rWhh,
                            const float* rbih, const float* rbhh,
                            float* out) {
    int idx = blockIdx.x * blockDim.x + threadIdx.x;   // 393216 threads
    if (idx == 0) *out = 0.f;
    if (idx < 3 * N_DOCS * HID) (&g_acc[0][0][0])[idx] = 0.f;

    if (idx < 2 * GATES) {
        int bm = idx >> 10, jb = idx & 1023;
        int jbo = perm_to_orig(jb);
        const float* bih = bm ? rbih : cbih;
        const float* bhh = bm ? rbhh : cbhh;
        g_bias[bm][jb] = bih[jbo] + bhh[jbo];
    }

    int lane = idx & 31;
    int ntg  = (idx >> 5) & 127;
    int q    = idx >> 12;
    int tg = lane & 3, gg = lane >> 2;
    int jo = perm_to_orig(ntg * 8 + gg);

    if (idx < 2 * NKT_X * 128 * 32) {           // Wih pack (k 0..299 pad 320)
        int kt  = q % NKT_X;
        int mat = q / NKT_X;
        const float* Wih = mat ? rWih : cWih;
        int k0 = kt * 32 + 4 * tg;
        float v[8];
        #pragma unroll
        for (int i = 0; i < 8; i++) {
            int k = k0 + (i >> 2) * 16 + (i & 3);
            v[i] = (k < EMBD) ? SCL * Wih[jo * EMBD + k] : 0.f;
        }
        uint2 w2;
        w2.x = pack4_e4m3(v[0], v[1], v[2], v[3]);
        w2.y = pack4_e4m3(v[4], v[5], v[6], v[7]);
        g_Wih[mat][kt][ntg][lane] = w2;
    }
    if (idx < 2 * NKT_H * 128 * 32) {           // Whh pack, pair-interleaved
        int kt  = q % NKT_H;
        int mat = q / NKT_H;
        const float* Whh = mat ? rWhh : cWhh;
        int k0 = kt * 32 + 4 * tg;
        float v[8];
        #pragma unroll
        for (int i = 0; i < 8; i++) {
            int k = k0 + (i >> 2) * 16 + (i & 3);
            v[i] = SCL * Whh[jo * HID + k];
        }
        uint2 w2;
        w2.x = pack4_e4m3(v[0], v[1], v[2], v[3]);
        w2.y = pack4_e4m3(v[4], v[5], v[6], v[7]);
        g_Whh2[mat][kt][ntg >> 1][lane][ntg & 1] = w2;
    }
}

__global__ void dummy_kernel() {}

// ---------------- xproj: 32 vocab rows/block, 256 threads, occ 2 (R13 shape) ----------------
__global__ void __launch_bounds__(256, 2)
xproj_kernel(const float* emb) {
    __shared__ uint8_t As[32 * XSB];       // 10752 B
    int bid = blockIdx.x;                  // 2 * 1563
    int mat = bid >= 1563;
    int vbase = (bid - mat * 1563) * 32;

    int tid = threadIdx.x;
    int w = tid >> 5, lane = tid & 31;
    int tg = lane & 3, gg = lane >> 2;

    for (int i = tid; i < 32 * XSB / 4; i += 256) ((uint32_t*)As)[i] = 0u;
    __syncthreads();

    {   // gather embeddings -> fp8 (x16): 8 threads per row
        int m = tid >> 3, ts = tid & 7;
        int row = vbase + m; if (row >= VOCAB) row = 0;
        const float4* erow = (const float4*)(emb + (size_t)row * EMBD);
        uint32_t* arow = (uint32_t*)(As + m * XSB);
        for (int kk = ts; kk < EMBD / 4; kk += 8) {
            float4 v = __ldg(&erow[kk]);
            arow[kk] = pack4_e4m3(SCL * v.x, SCL * v.y, SCL * v.z, SCL * v.w);
        }
    }
    __syncthreads();

    const uint32_t* Aw = (const uint32_t*)As;
    const int a_base = gg * XKW + tg;

    #pragma unroll
    for (int h = 0; h < 2; h++) {
        int nt_base = (w << 4) + (h << 3);
        const uint2* Bp = &g_Wih[mat][0][0][0] + nt_base * 32 + lane;

        float acc[2][8][4];
        #pragma unroll
        for (int mt = 0; mt < 2; mt++)
            #pragma unroll
            for (int nt = 0; nt < 8; nt++)
                #pragma unroll
                for (int i = 0; i < 4; i++) acc[mt][nt][i] = 0.f;

        uint2 bb[8];
        #pragma unroll
        for (int nt = 0; nt < 8; nt++) bb[nt] = __ldg(Bp + nt * 32);
        #pragma unroll
        for (int kt = 0; kt < NKT_X; kt++) {
            uint2 bn[8];
            if (kt < NKT_X - 1) {
                const uint2* bk2 = Bp + (size_t)(kt + 1) * 128 * 32;
                #pragma unroll
                for (int nt = 0; nt < 8; nt++) bn[nt] = __ldg(bk2 + nt * 32);
            }
            uint32_t a[2][4];
            int ab = a_base + kt * 8;
            #pragma unroll
            for (int mt = 0; mt < 2; mt++) {
                int o = ab + mt * 16 * XKW;
                a[mt][0] = Aw[o];
                a[mt][1] = Aw[o + 8 * XKW];
                a[mt][2] = Aw[o + 4];
                a[mt][3] = Aw[o + 8 * XKW + 4];
            }
            #pragma unroll
            for (int nt = 0; nt < 8; nt++) {
                mma16832(acc[0][nt], a[0], bb[nt].x, bb[nt].y);
                mma16832(acc[1][nt], a[1], bb[nt].x, bb[nt].y);
            }
            #pragma unroll
            for (int nt = 0; nt < 8; nt++) bb[nt] = bn[nt];
        }

        // epilogue: +bias, store bf16x2 in fragment-word order
        #pragma unroll
        for (int nt = 0; nt < 8; nt++) {
            int tile = nt_base + nt;
            int jc = (tile << 3) + (tg << 1);
            int wp = ((tile >> 1) << 3) + (tg << 1) + (tile & 1);   // fragment word index
            float b0 = g_bias[mat][jc], b1 = g_bias[mat][jc + 1];
            #pragma unroll
            for (int mt = 0; mt < 2; mt++) {
                int r0 = vbase + (mt << 4) + gg;
                int r1 = r0 + 8;
                if (r0 < VOCAB)
                    g_xprojF[mat][r0][wp] =
                        pack_bf16x2(acc[mt][nt][0] * ISCL + b0, acc[mt][nt][1] * ISCL + b1);
                if (r1 < VOCAB)
                    g_xprojF[mat][r1][wp] =
                        pack_bf16x2(acc[mt][nt][2] * ISCL + b0, acc[mt][nt][3] * ISCL + b1);
            }
        }
    }
}

// ---------------- main recurrent LSTM kernel: 2-CTA cluster split-N, sleep-wait sync ----------------
__global__ void __cluster_dims__(2, 1, 1) __launch_bounds__(NT, 2)
lstm_kernel(const int* colT, const int* rowT, const int* negT,
            const int* clen, const int* rlen, const int* nlen,
            const int* cref, const int* rref, const int* nref) {
    // A buffers in fragment-major order: byte addr = kt*512 + lane*16 + j*4 + b
    __shared__ __align__(16) uint8_t  AsF0[NKT_H * 512];     // 4096
    __shared__ __align__(16) uint8_t  AsF1[NKT_H * 512];     // 4096
    __shared__ __nv_bfloat16  Hs[MCH * 264];         // 8448
    __shared__ int            toksAll[MCH * T_COL];  // 4096
    __shared__ int            lensS[MCH];
    __shared__ int            refS[MCH];
    __shared__ uint64_t       mbar;

    uint32_t rank;
    asm("mov.u32 %0, %%cluster_ctarank;" : "=r"(rank));

    // LPT map on cluster id (CLC contiguous placement: cluster c co-resident with c+74)
    int cid = blockIdx.x >> 1;
    int task, chunk;
    if (cid < 74)        { task = 0; chunk = cid; }           // long cols 0..73
    else if (cid < 148)  { task = 0; chunk = 329 - cid; }     // 255..182 (pairs long)
    else if (cid < 222)  { task = 0; chunk = cid - 74; }      // 74..147
    else if (cid < 256)  { task = 0; chunk = 403 - cid; }     // 181..148
    else { int s = cid - 256; task = 1 + (s & 1); chunk = s >> 1; }
    int n0 = chunk * MCH;

    const int* toks; const int* lens; const int* refs; int T; int mat;
    if (task == 0)      { toks = colT; lens = clen; refs = cref; T = T_COL; mat = 0; }
    else if (task == 1) { toks = rowT; lens = rlen; refs = rref; T = T_ROW; mat = 1; }
    else                { toks = negT; lens = nlen; refs = nref; T = T_ROW; mat = 1; }

    int tid = threadIdx.x;
    int w = tid >> 5, lane = tid & 31;
    int tg = lane & 3, gg = lane >> 2;

    // init: zero AsF0; load all tokens + lens; init mbarrier
    for (int i = tid; i < NKT_H * 512 / 4; i += NT) ((uint32_t*)AsF0)[i] = 0u;
    for (int i = tid; i < MCH * T; i += NT) toksAll[i] = toks[n0 * T + i];
    if (tid < MCH) lensS[tid] = lens[n0 + tid];
    uint32_t mbarA = smem_u32(&mbar);
    if (tid == 0) {
        asm volatile("mbarrier.init.shared.b64 [%0], %1;" :: "r"(mbarA), "r"(2 * NT) : "memory");
    }

    // peer addresses via mapa
    uint32_t peer = rank ^ 1u;
    uint32_t myAs0 = smem_u32(AsF0), myAs1 = smem_u32(AsF1);
    uint32_t pAs0, pAs1, pMbar;
    asm("mapa.shared::cluster.u32 %0, %1, %2;" : "=r"(pAs0) : "r"(myAs0), "r"(peer));
    asm("mapa.shared::cluster.u32 %0, %1, %2;" : "=r"(pAs1) : "r"(myAs1), "r"(peer));
    asm("mapa.shared::cluster.u32 %0, %1, %2;" : "=r"(pMbar) : "r"(mbarA), "r"(peer));

    // cluster sync: mbarriers + zeroed A visible before any arrivals / reads
    asm volatile("barrier.cluster.arrive.aligned;" ::: "memory");
    asm volatile("barrier.cluster.wait.aligned;" ::: "memory");

    int maxlen = lensS[0];    // lengths sorted descending (same for both CTAs)
    int len0 = lensS[gg], len1 = lensS[gg + 8];

    const uint32_t* xpF = &g_xprojF[mat][0][0];
    const uint4* Bq = (const uint4*)&g_Whh2[mat][0][0][0][0];  // [kt*64 + pair]*32 + lane
    int p0 = (int)rank * 32 + (w << 2);    // this warp's 4 global pairs

    // my contiguous half of the A buffer: bytes [rank*2048, rank*2048+2048)
    uint32_t xoff = ((uint32_t)rank << 11) + ((uint32_t)tid << 3);

    // cell state in registers: [pair 0..3][row r]
    float creg[4][2];
    #pragma unroll
    for (int p = 0; p < 4; p++) { creg[p][0] = 0.f; creg[p][1] = 0.f; }

    for (int t = 0; t < maxlen; t++) {
        const uint8_t* ArF = (t & 1) ? AsF1 : AsF0;
        uint8_t*       AwF = (t & 1) ? AsF0 : AsF1;
        uint32_t       pAw = (t & 1) ? pAs0 : pAs1;
        const uint4*   Ar4 = (const uint4*)ArF;

        int tk0 = toksAll[gg * T + t];
        int tk1 = toksAll[(gg + 8) * T + t];
        const uint32_t* xp0w = xpF + (size_t)tk0 * 512;
        const uint32_t* xp1w = xpF + (size_t)tk1 * 512;

        // gx: one LDG.64 per (pair, token)
        uint2 gq0[4], gq1[4];
        #pragma unroll
        for (int pp = 0; pp < 4; pp++) {
            int woff = ((p0 + pp) << 3) + (tg << 1);
            gq0[pp] = __ldg((const uint2*)(xp0w + woff));
            gq1[pp] = __ldg((const uint2*)(xp1w + woff));
        }

        float acc[8][4];
        #pragma unroll
        for (int nt = 0; nt < 8; nt++)
            #pragma unroll
            for (int i = 0; i < 4; i++) acc[nt][i] = 0.f;

        // 2-stage B pipeline: 4 LDG.128 per kt (one per pair)
        uint4 bb[4], bn[4];
        #pragma unroll
        for (int pp = 0; pp < 4; pp++) bb[pp] = __ldg(&Bq[(0 * 64 + p0 + pp) * 32 + lane]);
        #pragma unroll
        for (int kt = 0; kt < NKT_H; kt++) {
            if (kt < NKT_H - 1) {
                #pragma unroll
                for (int pp = 0; pp < 4; pp++)
                    bn[pp] = __ldg(&Bq[((kt + 1) * 64 + p0 + pp) * 32 + lane]);
            }
            uint4 av = Ar4[kt * 32 + lane];          // one LDS.128: a0..a3
            uint32_t a[4] = {av.x, av.y, av.z, av.w};
            #pragma unroll
            for (int pp = 0; pp < 4; pp++) {
                mma16832(acc[2 * pp],     a, bb[pp].x, bb[pp].y);
                mma16832(acc[2 * pp + 1], a, bb[pp].z, bb[pp].w);
            }
            #pragma unroll
            for (int pp = 0; pp < 4; pp++) bb[pp] = bn[pp];
        }

        // epilogue: shuffle-free; local writes only
        #pragma unroll
        for (int pp = 0; pp < 4; pp++) {
            int P = p0 + pp;
            int abase = ((P >> 3) << 9) + ((gg << 2) + (P & 3)) * 16
                      + (((P >> 2) & 1) << 3) + tg;
            #pragma unroll
            for (int r = 0; r < 2; r++) {
                int cb = r << 1;
                uint32_t ew = r ? gq1[pp].x : gq0[pp].x;
                uint32_t ow = r ? gq1[pp].y : gq0[pp].y;
                float2 e2 = __bfloat1622float2(*(__nv_bfloat162*)&ew);
                float2 o2 = __bfloat1622float2(*(__nv_bfloat162*)&ow);
                float pi = acc[2 * pp][cb]     * ISCL + e2.x;
                float pf = acc[2 * pp][cb + 1] * ISCL + e2.y;
                float pg = acc[2 * pp + 1][cb]     * ISCL + o2.x;
                float po = acc[2 * pp + 1][cb + 1] * ISCL + o2.y;
                int lenm = r ? len1 : len0;
                int ai = abase + (r << 2);
                uint8_t val;
                if (t < lenm) {
                    float cn = fsigm(pf) * creg[pp][r] + fsigm(pi) * ftanh(pg);
                    creg[pp][r] = cn;
                    float hn = fsigm(po) * ftanh(cn);
                    val = f_to_e4m3(SCL * hn);
                    if (t == lenm - 1) {
                        int mrow = gg + (r << 3);
                        int u = (P << 2) + tg;
                        Hs[mrow * 264 + u] = __float2bfloat16(hn);
                    }
                } else {
                    val = ArF[ai];   // carry frozen h forward
                }
                AwF[ai] = val;
            }
        }

        // local writes visible, then bulk-copy my contiguous 2KB half to peer
        __syncthreads();
        {
            uint64_t v64 = *(const uint64_t*)(AwF + xoff);
            asm volatile("st.shared::cluster.u64 [%0], %1;"
                         :: "r"(pAw + xoff), "l"(v64) : "memory");
        }

        // per-step cluster sync via mbarrier (release orders the remote stores);
        // HINTED try_wait -> HW sleep instead of poll (frees issue slots)
        asm volatile("mbarrier.arrive.release.cluster.shared::cluster.b64 _, [%0];"
                     :: "r"(pMbar) : "memory");
        asm volatile("mbarrier.arrive.release.cluster.shared::cta.b64 _, [%0];"
                     :: "r"(mbarA) : "memory");
        {
            uint32_t par = (uint32_t)(t & 1);
            uint32_t done = 0;
            while (!done) {
                asm volatile(
                    "{\n\t.reg .pred p;\n\t"
                    "mbarrier.try_wait.parity.acquire.cluster.shared::cta.b64 p, [%1], %2, 0x989680;\n\t"
                    "selp.b32 %0, 1, 0, p;\n\t}"
                    : "=r"(done) : "r"(mbarA), "r"(par) : "memory");
            }
        }
    }

    // scatter this CTA's half of final h into doc accumulators
    if (tid < MCH) refS[tid] = refs[n0 + tid];
    __syncthreads();
    float* accb = &g_acc[task][0][0];
    for (int idx = tid; idx < MCH * 128; idx += NT) {
        int m = idx >> 7;
        int u = (int)rank * 128 + (idx & 127);
        atomicAdd(&accb[refS[m] * HID + u], __bfloat162float(Hs[m * 264 + u]));
    }

    // final cluster sync before teardown
    asm volatile("barrier.cluster.arrive.aligned;" ::: "memory");
    asm volatile("barrier.cluster.wait.aligned;" ::: "memory");
}

// ---------------- loss ----------------
__global__ void loss_kernel(float* out) {
    int d = blockIdx.x;
    float cv = g_acc[0][d][threadIdx.x], rv = g_acc[1][d][threadIdx.x], nv = g_acc[2][d][threadIdx.x];
    float p = cv * rv, q = cv * nv;
    #pragma unroll
    for (int o = 16; o; o >>= 1) {
        p += __shfl_xor_sync(0xffffffffu, p, o);
        q += __shfl_xor_sync(0xffffffffu, q, o);
    }
    __shared__ float sp[8], sq[8];
    int w = threadIdx.x >> 5, l = threadIdx.x & 31;
    if (l == 0) { sp[w] = p; sq[w] = q; }
    __syncthreads();
    if (threadIdx.x == 0) {
        float P = 0.f, Q = 0.f;
        #pragma unroll
        for (int i = 0; i < 8; i++) { P += sp[i]; Q += sq[i]; }
        float x = P - Q;
        float lz = fmaxf(-x, 0.f) + log1pf(expf(-fabsf(x)));
        if (d == 0) lz += (float)((N_SEQ - N_DOCS) * 0.6931471805599453);
        atomicAdd(out, lz);
    }
}

// ---------------- launch ----------------
extern "C" void kernel_launch(void* const* d_in, const int* in_sizes, int n_in,
                              void* d_out, int out_size) {
    const int*   col   = (const int*)d_in[0];
    const int*   row   = (const int*)d_in[1];
    const int*   rng   = (const int*)d_in[2];
    const int*   clen  = (const int*)d_in[3];
    const int*   rlen  = (const int*)d_in[4];
    const int*   nlen  = (const int*)d_in[5];
    const int*   cref  = (const int*)d_in[6];
    const int*   rref  = (const int*)d_in[7];
    const int*   nref  = (const int*)d_in[8];
    const float* emb   = (const float*)d_in[9];
    const float* cWih  = (const float*)d_in[10];
    const float* cWhh  = (const float*)d_in[11];
    const float* cbih  = (const float*)d_in[12];
    const float* cbhh  = (const float*)d_in[13];
    const float* rWih  = (const float*)d_in[14];
    const float* rWhh  = (const float*)d_in[15];
    const float* rbih  = (const float*)d_in[16];
    const float* rbhh  = (const float*)d_in[17];
    float* out = (float*)d_out;

    prep_kernel<<<1536, 256>>>(cWih, cWhh, cbih, cbhh, rWih, rWhh, rbih, rbhh, out);
    xproj_kernel<<<2 * 1563, 256>>>(emb);
    dummy_kernel<<<1, 32>>>();
    lstm_kernel<<<1536, NT>>>(col, row, rng, clen, rlen, nlen, cref, rref, nref);
    loss_kernel<<<N_DOCS, 256>>>(out);
}

// round 16
// speedup vs baseline: 1.1410x; 1.0830x over previous
#include <cuda_runtime.h>
#include <cuda_bf16.h>
#include <cuda_fp8.h>
#include <math.h>
#include <stdint.h>

// Problem constants
#define VOCAB   50000
#define N_SEQ   4096
#define N_DOCS  512
#define EMBD    300
#define HID     256
#define GATES   1024
#define T_COL   64
#define T_ROW   16

#define MCH     16          // sequences per chunk (one 2-CTA cluster)
#define NT      256         // 8 warps per CTA

#define NKT_H   8
// xproj A (emb, fp8): k=300 pad 320 -> 10 kt, row stride 336 B (84 words)
#define NKT_X   10
#define XKW     84
#define XSB     336

#define SCL     16.0f
#define ISCL    0.00390625f // 1/256

// ---------------- device scratch ----------------
// Whh fragments, pair-interleaved for LDG.128: [mat][kt][pair(64)][lane][2 tiles]
__device__ uint2  g_Whh2[2][NKT_H][64][32][2];
__device__ uint2  g_Wih[2][NKT_X][128][32];    // fp8 B fragments (x-proj)
__device__ float  g_bias[2][GATES];
// xproj in fragment-word order: word w' = P*8 + tg*2 + eo  (P=pair, eo: 0=(i,f),1=(g,o))
__device__ uint32_t g_xprojF[2][VOCAB][512];   // 204.8 MB
__device__ float  g_acc[3][N_DOCS][HID];

// permuted column -> original gate column:
//   p = j'>>3 (tile), c = j'&7;  gate = (p&1)*2 + (c&1);  unit = 4*(p>>1) + (c>>1)
__device__ __forceinline__ int perm_to_orig(int jp) {
    int p = jp >> 3, c = jp & 7;
    int gate = ((p & 1) << 1) | (c & 1);
    int unit = ((p >> 1) << 2) | (c >> 1);
    return gate * 256 + unit;
}

// ---------------- helpers ----------------
__device__ __forceinline__ float ftanh(float x) {
    float y; asm("tanh.approx.f32 %0, %1;" : "=f"(y) : "f"(x)); return y;
}
__device__ __forceinline__ float fsigm(float x) {
    return 0.5f * ftanh(0.5f * x) + 0.5f;
}
__device__ __forceinline__ uint32_t pack4_e4m3(float v0, float v1, float v2, float v3) {
    uint16_t lo, hi;
    asm("cvt.rn.satfinite.e4m3x2.f32 %0, %1, %2;" : "=h"(lo) : "f"(v1), "f"(v0));
    asm("cvt.rn.satfinite.e4m3x2.f32 %0, %1, %2;" : "=h"(hi) : "f"(v3), "f"(v2));
    return (uint32_t)lo | ((uint32_t)hi << 16);
}
__device__ __forceinline__ uint8_t f_to_e4m3(float v) {
    uint16_t r;
    asm("cvt.rn.satfinite.e4m3x2.f32 %0, %1, %2;" : "=h"(r) : "f"(0.f), "f"(v));
    return (uint8_t)r;
}
__device__ __forceinline__ uint32_t pack_bf16x2(float lo, float hi) {
    uint32_t r;
    asm("cvt.rn.bf16x2.f32 %0, %1, %2;" : "=r"(r) : "f"(hi), "f"(lo));
    return r;
}
__device__ __forceinline__ void mma16832(float* c, const uint32_t* a, uint32_t b0, uint32_t b1) {
    asm volatile(
        "mma.sync.aligned.m16n8k32.row.col.f32.e4m3.e4m3.f32 "
        "{%0,%1,%2,%3},{%4,%5,%6,%7},{%8,%9},{%0,%1,%2,%3};"
        : "+f"(c[0]), "+f"(c[1]), "+f"(c[2]), "+f"(c[3])
        : "r"(a[0]), "r"(a[1]), "r"(a[2]), "r"(a[3]), "r"(b0), "r"(b1));
}
__device__ __forceinline__ uint32_t smem_u32(const void* p) {
    uint32_t a;
    asm("{ .reg .u64 t; cvta.to.shared.u64 t, %1; cvt.u32.u64 %0, t; }" : "=r"(a) : "l"(p));
    return a;
}

// ---------------- prep: pack weights + bias, zero accumulators ----------------
__global__ void prep_kernel(const float* cWih, const float* cWhh,
                            const float* cbih, const float* cbhh,
                            const float* rWih, const float* rWhh,
                            const float* rbih, const float* rbhh,
                            float* out) {
    int idx = blockIdx.x * blockDim.x + threadIdx.x;   // 393216 threads
    if (idx == 0) *out = 0.f;
    if (idx < 3 * N_DOCS * HID) (&g_acc[0][0][0])[idx] = 0.f;

    if (idx < 2 * GATES) {
        int bm = idx >> 10, jb = idx & 1023;
        int jbo = perm_to_orig(jb);
        const float* bih = bm ? rbih : cbih;
        const float* bhh = bm ? rbhh : cbhh;
        g_bias[bm][jb] = bih[jbo] + bhh[jbo];
    }

    int lane = idx & 31;
    int ntg  = (idx >> 5) & 127;
    int q    = idx >> 12;
    int tg = lane & 3, gg = lane >> 2;
    int jo = perm_to_orig(ntg * 8 + gg);

    if (idx < 2 * NKT_X * 128 * 32) {           // Wih pack (k 0..299 pad 320)
        int kt  = q % NKT_X;
        int mat = q / NKT_X;
        const float* Wih = mat ? rWih : cWih;
        int k0 = kt * 32 + 4 * tg;
        float v[8];
        #pragma unroll
        for (int i = 0; i < 8; i++) {
            int k = k0 + (i >> 2) * 16 + (i & 3);
            v[i] = (k < EMBD) ? SCL * Wih[jo * EMBD + k] : 0.f;
        }
        uint2 w2;
        w2.x = pack4_e4m3(v[0], v[1], v[2], v[3]);
        w2.y = pack4_e4m3(v[4], v[5], v[6], v[7]);
        g_Wih[mat][kt][ntg][lane] = w2;
    }
    if (idx < 2 * NKT_H * 128 * 32) {           // Whh pack, pair-interleaved
        int kt  = q % NKT_H;
        int mat = q / NKT_H;
        const float* Whh = mat ? rWhh : cWhh;
        int k0 = kt * 32 + 4 * tg;
        float v[8];
        #pragma unroll
        for (int i = 0; i < 8; i++) {
            int k = k0 + (i >> 2) * 16 + (i & 3);
            v[i] = SCL * Whh[jo * HID + k];
        }
        uint2 w2;
        w2.x = pack4_e4m3(v[0], v[1], v[2], v[3]);
        w2.y = pack4_e4m3(v[4], v[5], v[6], v[7]);
        g_Whh2[mat][kt][ntg >> 1][lane][ntg & 1] = w2;
    }
}

__global__ void dummy_kernel() {}

// ---------------- xproj: 32 vocab rows/block, 256 threads, occ 2 ----------------
__global__ void __launch_bounds__(256, 2)
xproj_kernel(const float* emb) {
    __shared__ uint8_t As[32 * XSB];       // 10752 B
    int bid = blockIdx.x;                  // 2 * 1563
    int mat = bid >= 1563;
    int vbase = (bid - mat * 1563) * 32;

    int tid = threadIdx.x;
    int w = tid >> 5, lane = tid & 31;
    int tg = lane & 3, gg = lane >> 2;

    for (int i = tid; i < 32 * XSB / 4; i += 256) ((uint32_t*)As)[i] = 0u;
    __syncthreads();

    {   // gather embeddings -> fp8 (x16): 8 threads per row
        int m = tid >> 3, ts = tid & 7;
        int row = vbase + m; if (row >= VOCAB) row = 0;
        const float4* erow = (const float4*)(emb + (size_t)row * EMBD);
        uint32_t* arow = (uint32_t*)(As + m * XSB);
        for (int kk = ts; kk < EMBD / 4; kk += 8) {
            float4 v = __ldg(&erow[kk]);
            arow[kk] = pack4_e4m3(SCL * v.x, SCL * v.y, SCL * v.z, SCL * v.w);
        }
    }
    __syncthreads();

    const uint32_t* Aw = (const uint32_t*)As;
    const int a_base = gg * XKW + tg;

    #pragma unroll
    for (int h = 0; h < 2; h++) {
        int nt_base = (w << 4) + (h << 3);
        const uint2* Bp = &g_Wih[mat][0][0][0] + nt_base * 32 + lane;

        float acc[2][8][4];
        #pragma unroll
        for (int mt = 0; mt < 2; mt++)
            #pragma unroll
            for (int nt = 0; nt < 8; nt++)
                #pragma unroll
                for (int i = 0; i < 4; i++) acc[mt][nt][i] = 0.f;

        uint2 bb[8];
        #pragma unroll
        for (int nt = 0; nt < 8; nt++) bb[nt] = __ldg(Bp + nt * 32);
        #pragma unroll
        for (int kt = 0; kt < NKT_X; kt++) {
            uint2 bn[8];
            if (kt < NKT_X - 1) {
                const uint2* bk2 = Bp + (size_t)(kt + 1) * 128 * 32;
                #pragma unroll
                for (int nt = 0; nt < 8; nt++) bn[nt] = __ldg(bk2 + nt * 32);
            }
            uint32_t a[2][4];
            int ab = a_base + kt * 8;
            #pragma unroll
            for (int mt = 0; mt < 2; mt++) {
                int o = ab + mt * 16 * XKW;
                a[mt][0] = Aw[o];
                a[mt][1] = Aw[o + 8 * XKW];
                a[mt][2] = Aw[o + 4];
                a[mt][3] = Aw[o + 8 * XKW + 4];
            }
            #pragma unroll
            for (int nt = 0; nt < 8; nt++) {
                mma16832(acc[0][nt], a[0], bb[nt].x, bb[nt].y);
                mma16832(acc[1][nt], a[1], bb[nt].x, bb[nt].y);
            }
            #pragma unroll
            for (int nt = 0; nt < 8; nt++) bb[nt] = bn[nt];
        }

        // epilogue: +bias, store bf16x2 in fragment-word order
        #pragma unroll
        for (int nt = 0; nt < 8; nt++) {
            int tile = nt_base + nt;
            int jc = (tile << 3) + (tg << 1);
            int wp = ((tile >> 1) << 3) + (tg << 1) + (tile & 1);   // fragment word index
            float b0 = g_bias[mat][jc], b1 = g_bias[mat][jc + 1];
            #pragma unroll
            for (int mt = 0; mt < 2; mt++) {
                int r0 = vbase + (mt << 4) + gg;
                int r1 = r0 + 8;
                if (r0 < VOCAB)
                    g_xprojF[mat][r0][wp] =
                        pack_bf16x2(acc[mt][nt][0] * ISCL + b0, acc[mt][nt][1] * ISCL + b1);
                if (r1 < VOCAB)
                    g_xprojF[mat][r1][wp] =
                        pack_bf16x2(acc[mt][nt][2] * ISCL + b0, acc[mt][nt][3] * ISCL + b1);
            }
        }
    }
}

// ---------------- main recurrent LSTM kernel: 2-CTA cluster split-N,
//                  mbarrier-only per-step sync + pre-copy frozen rows ----------------
__global__ void __cluster_dims__(2, 1, 1) __launch_bounds__(NT, 2)
lstm_kernel(const int* colT, const int* rowT, const int* negT,
            const int* clen, const int* rlen, const int* nlen,
            const int* cref, const int* rref, const int* nref) {
    // A buffers in fragment-major order: byte addr = kt*512 + lane*16 + j*4 + b
    __shared__ __align__(16) uint8_t  AsF0[NKT_H * 512];     // 4096
    __shared__ __align__(16) uint8_t  AsF1[NKT_H * 512];     // 4096
    __shared__ __nv_bfloat16  Hs[MCH * 264];         // 8448
    __shared__ int            toksAll[MCH * T_COL];  // 4096
    __shared__ int            lensS[MCH];
    __shared__ int            refS[MCH];
    __shared__ uint64_t       mbar;

    uint32_t rank;
    asm("mov.u32 %0, %%cluster_ctarank;" : "=r"(rank));

    // LPT map on cluster id (CLC contiguous placement: cluster c co-resident with c+74)
    int cid = blockIdx.x >> 1;
    int task, chunk;
    if (cid < 74)        { task = 0; chunk = cid; }           // long cols 0..73
    else if (cid < 148)  { task = 0; chunk = 329 - cid; }     // 255..182 (pairs long)
    else if (cid < 222)  { task = 0; chunk = cid - 74; }      // 74..147
    else if (cid < 256)  { task = 0; chunk = 403 - cid; }     // 181..148
    else { int s = cid - 256; task = 1 + (s & 1); chunk = s >> 1; }
    int n0 = chunk * MCH;

    const int* toks; const int* lens; const int* refs; int T; int mat;
    if (task == 0)      { toks = colT; lens = clen; refs = cref; T = T_COL; mat = 0; }
    else if (task == 1) { toks = rowT; lens = rlen; refs = rref; T = T_ROW; mat = 1; }
    else                { toks = negT; lens = nlen; refs = nref; T = T_ROW; mat = 1; }

    int tid = threadIdx.x;
    int w = tid >> 5, lane = tid & 31;
    int tg = lane & 3, gg = lane >> 2;

    // init: zero AsF0; load all tokens + lens; init mbarrier
    for (int i = tid; i < NKT_H * 512 / 4; i += NT) ((uint32_t*)AsF0)[i] = 0u;
    for (int i = tid; i < MCH * T; i += NT) toksAll[i] = toks[n0 * T + i];
    if (tid < MCH) lensS[tid] = lens[n0 + tid];
    uint32_t mbarA = smem_u32(&mbar);
    if (tid == 0) {
        asm volatile("mbarrier.init.shared.b64 [%0], %1;" :: "r"(mbarA), "r"(2 * NT) : "memory");
    }

    // peer addresses via mapa
    uint32_t peer = rank ^ 1u;
    uint32_t myAs0 = smem_u32(AsF0), myAs1 = smem_u32(AsF1);
    uint32_t pAs0, pAs1, pMbar;
    asm("mapa.shared::cluster.u32 %0, %1, %2;" : "=r"(pAs0) : "r"(myAs0), "r"(peer));
    asm("mapa.shared::cluster.u32 %0, %1, %2;" : "=r"(pAs1) : "r"(myAs1), "r"(peer));
    asm("mapa.shared::cluster.u32 %0, %1, %2;" : "=r"(pMbar) : "r"(mbarA), "r"(peer));

    // cluster sync: mbarriers + zeroed A visible before any arrivals / reads
    asm volatile("barrier.cluster.arrive.aligned;" ::: "memory");
    asm volatile("barrier.cluster.wait.aligned;" ::: "memory");

    int maxlen = lensS[0];    // lengths sorted descending (same for both CTAs)
    int len0 = lensS[gg], len1 = lensS[gg + 8];

    const uint32_t* xpF = &g_xprojF[mat][0][0];
    const uint4* Bq = (const uint4*)&g_Whh2[mat][0][0][0][0];  // [kt*64 + pair]*32 + lane
    int p0 = (int)rank * 32 + (w << 2);    // this warp's 4 global pairs

    // warp-own 8-byte unit inside its exclusive 256B write region:
    //   kt-block = rank*4 + (w>>1); per-lane unit = lane*16 + (w&1)*8
    uint32_t regoff = (((uint32_t)rank * 4u + (uint32_t)(w >> 1)) << 9)
                    + ((uint32_t)lane << 4) + ((uint32_t)(w & 1) << 3);

    // cell state in registers: [pair 0..3][row r]
    float creg[4][2];
    #pragma unroll
    for (int p = 0; p < 4; p++) { creg[p][0] = 0.f; creg[p][1] = 0.f; }

    for (int t = 0; t < maxlen; t++) {
        const uint8_t* ArF = (t & 1) ? AsF1 : AsF0;
        uint8_t*       AwF = (t & 1) ? AsF0 : AsF1;
        uint32_t       pAw = (t & 1) ? pAs0 : pAs1;
        const uint4*   Ar4 = (const uint4*)ArF;

        // pre-copy own 8-byte unit (frozen-row default); AwF(t)==ArF(t-1), drained
        *(uint64_t*)(AwF + regoff) = *(const uint64_t*)(ArF + regoff);
        __syncwarp();   // order pre-copy before this warp's epilogue overwrites

        int tk0 = toksAll[gg * T + t];
        int tk1 = toksAll[(gg + 8) * T + t];
        const uint32_t* xp0w = xpF + (size_t)tk0 * 512;
        const uint32_t* xp1w = xpF + (size_t)tk1 * 512;

        // gx: one LDG.64 per (pair, token)
        uint2 gq0[4], gq1[4];
        #pragma unroll
        for (int pp = 0; pp < 4; pp++) {
            int woff = ((p0 + pp) << 3) + (tg << 1);
            gq0[pp] = __ldg((const uint2*)(xp0w + woff));
            gq1[pp] = __ldg((const uint2*)(xp1w + woff));
        }

        float acc[8][4];
        #pragma unroll
        for (int nt = 0; nt < 8; nt++)
            #pragma unroll
            for (int i = 0; i < 4; i++) acc[nt][i] = 0.f;

        // 2-stage B pipeline: 4 LDG.128 per kt (one per pair)
        uint4 bb[4], bn[4];
        #pragma unroll
        for (int pp = 0; pp < 4; pp++) bb[pp] = __ldg(&Bq[(0 * 64 + p0 + pp) * 32 + lane]);
        #pragma unroll
        for (int kt = 0; kt < NKT_H; kt++) {
            if (kt < NKT_H - 1) {
                #pragma unroll
                for (int pp = 0; pp < 4; pp++)
                    bn[pp] = __ldg(&Bq[((kt + 1) * 64 + p0 + pp) * 32 + lane]);
            }
            uint4 av = Ar4[kt * 32 + lane];          // one LDS.128: a0..a3
            uint32_t a[4] = {av.x, av.y, av.z, av.w};
            #pragma unroll
            for (int pp = 0; pp < 4; pp++) {
                mma16832(acc[2 * pp],     a, bb[pp].x, bb[pp].y);
                mma16832(acc[2 * pp + 1], a, bb[pp].z, bb[pp].w);
            }
            #pragma unroll
            for (int pp = 0; pp < 4; pp++) bb[pp] = bn[pp];
        }

        // epilogue: active rows only (frozen rows already pre-copied)
        #pragma unroll
        for (int pp = 0; pp < 4; pp++) {
            int P = p0 + pp;
            int abase = ((P >> 3) << 9) + ((gg << 2) + (P & 3)) * 16
                      + (((P >> 2) & 1) << 3) + tg;
            #pragma unroll
            for (int r = 0; r < 2; r++) {
                int lenm = r ? len1 : len0;
                if (t < lenm) {
                    int cb = r << 1;
                    uint32_t ew = r ? gq1[pp].x : gq0[pp].x;
                    uint32_t ow = r ? gq1[pp].y : gq0[pp].y;
                    float2 e2 = __bfloat1622float2(*(__nv_bfloat162*)&ew);
                    float2 o2 = __bfloat1622float2(*(__nv_bfloat162*)&ow);
                    float pi = acc[2 * pp][cb]     * ISCL + e2.x;
                    float pf = acc[2 * pp][cb + 1] * ISCL + e2.y;
                    float pg = acc[2 * pp + 1][cb]     * ISCL + o2.x;
                    float po = acc[2 * pp + 1][cb + 1] * ISCL + o2.y;
                    float cn = fsigm(pf) * creg[pp][r] + fsigm(pi) * ftanh(pg);
                    creg[pp][r] = cn;
                    float hn = fsigm(po) * ftanh(cn);
                    AwF[abase + (r << 2)] = f_to_e4m3(SCL * hn);
                    if (t == lenm - 1) {
                        int mrow = gg + (r << 3);
                        int u = (P << 2) + tg;
                        Hs[mrow * 264 + u] = __float2bfloat16(hn);
                    }
                }
            }
        }

        // warp-local visibility of the warp's region, then copy to peer
        __syncwarp();
        {
            uint64_t v64 = *(const uint64_t*)(AwF + regoff);
            asm volatile("st.shared::cluster.u64 [%0], %1;"
                         :: "r"(pAw + regoff), "l"(v64) : "memory");
        }

        // single per-step sync: release-arrive (peer + local), acquire-wait
        asm volatile("mbarrier.arrive.release.cluster.shared::cluster.b64 _, [%0];"
                     :: "r"(pMbar) : "memory");
        asm volatile("mbarrier.arrive.release.cluster.shared::cta.b64 _, [%0];"
                     :: "r"(mbarA) : "memory");
        {
            uint32_t par = (uint32_t)(t & 1);
            uint32_t done = 0;
            while (!done) {
                asm volatile(
                    "{\n\t.reg .pred p;\n\t"
                    "mbarrier.try_wait.parity.acquire.cluster.shared::cta.b64 p, [%1], %2, 0x989680;\n\t"
                    "selp.b32 %0, 1, 0, p;\n\t}"
                    : "=r"(done) : "r"(mbarA), "r"(par) : "memory");
            }
        }
    }

    // scatter this CTA's half of final h into doc accumulators
    if (tid < MCH) refS[tid] = refs[n0 + tid];
    __syncthreads();
    float* accb = &g_acc[task][0][0];
    for (int idx = tid; idx < MCH * 128; idx += NT) {
        int m = idx >> 7;
        int u = (int)rank * 128 + (idx & 127);
        atomicAdd(&accb[refS[m] * HID + u], __bfloat162float(Hs[m * 264 + u]));
    }

    // final cluster sync before teardown
    asm volatile("barrier.cluster.arrive.aligned;" ::: "memory");
    asm volatile("barrier.cluster.wait.aligned;" ::: "memory");
}

// ---------------- loss ----------------
__global__ void loss_kernel(float* out) {
    int d = blockIdx.x;
    float cv = g_acc[0][d][threadIdx.x], rv = g_acc[1][d][threadIdx.x], nv = g_acc[2][d][threadIdx.x];
    float p = cv * rv, q = cv * nv;
    #pragma unroll
    for (int o = 16; o; o >>= 1) {
        p += __shfl_xor_sync(0xffffffffu, p, o);
        q += __shfl_xor_sync(0xffffffffu, q, o);
    }
    __shared__ float sp[8], sq[8];
    int w = threadIdx.x >> 5, l = threadIdx.x & 31;
    if (l == 0) { sp[w] = p; sq[w] = q; }
    __syncthreads();
    if (threadIdx.x == 0) {
        float P = 0.f, Q = 0.f;
        #pragma unroll
        for (int i = 0; i < 8; i++) { P += sp[i]; Q += sq[i]; }
        float x = P - Q;
        float lz = fmaxf(-x, 0.f) + log1pf(expf(-fabsf(x)));
        if (d == 0) lz += (float)((N_SEQ - N_DOCS) * 0.6931471805599453);
        atomicAdd(out, lz);
    }
}

// ---------------- launch ----------------
extern "C" void kernel_launch(void* const* d_in, const int* in_sizes, int n_in,
                              void* d_out, int out_size) {
    const int*   col   = (const int*)d_in[0];
    const int*   row   = (const int*)d_in[1];
    const int*   rng   = (const int*)d_in[2];
    const int*   clen  = (const int*)d_in[3];
    const int*   rlen  = (const int*)d_in[4];
    const int*   nlen  = (const int*)d_in[5];
    const int*   cref  = (const int*)d_in[6];
    const int*   rref  = (const int*)d_in[7];
    const int*   nref  = (const int*)d_in[8];
    const float* emb   = (const float*)d_in[9];
    const float* cWih  = (const float*)d_in[10];
    const float* cWhh  = (const float*)d_in[11];
    const float* cbih  = (const float*)d_in[12];
    const float* cbhh  = (const float*)d_in[13];
    const float* rWih  = (const float*)d_in[14];
    const float* rWhh  = (const float*)d_in[15];
    const float* rbih  = (const float*)d_in[16];
    const float* rbhh  = (const float*)d_in[17];
    float* out = (float*)d_out;

    prep_kernel<<<1536, 256>>>(cWih, cWhh, cbih, cbhh, rWih, rWhh, rbih, rbhh, out);
    xproj_kernel<<<2 * 1563, 256>>>(emb);
    dummy_kernel<<<1, 32>>>();
    lstm_kernel<<<1536, NT>>>(col, row, rng, clen, rlen, nlen, cref, rref, nref);
    loss_kernel<<<N_DOCS, 256>>>(out);
}